// round 4
// baseline (speedup 1.0000x reference)
#include <cuda_runtime.h>
#include <math.h>

// CantorMoELayer — B=8, P=2048, D=1024, E=16, S=64, DK=128, H=16
// Key insight: fingerprint mask depends only on p; each position has 1-2 active
// experts; inactive experts contribute nothing (mw=0 and rec masked).
// One block per position, batch-register-blocked GEMVs -> each weight element
// loaded once per block.

namespace {

constexpr int P_  = 2048;
constexpr int D_  = 1024;
constexpr int E_  = 16;
constexpr int S_  = 64;
constexpr int DK_ = 128;
constexpr int H_  = 16;

__device__ __forceinline__ float sigm(float x) { return 1.0f / (1.0f + expf(-x)); }
__device__ __forceinline__ float gelu_exact(float x) {
    return 0.5f * x * (1.0f + erff(x * 0.70710678118654752440f));
}

__global__ void __launch_bounds__(256) cantor_moe_kernel(
    const float* __restrict__ x,
    const float* __restrict__ fingerprints,
    const float* __restrict__ ln_gamma,
    const float* __restrict__ ln_beta,
    const float* __restrict__ w1,
    const float* __restrict__ b1,
    const float* __restrict__ w2,
    const float* __restrict__ b2,
    const float* __restrict__ alpha,
    const float* __restrict__ wv,
    const float* __restrict__ penta,
    const float* __restrict__ betas,
    const float* __restrict__ wout,
    const float* __restrict__ pos_embed,
    const float* __restrict__ temperature,
    float* __restrict__ out)
{
    __shared__ float xnsm[8][D_];        // 32 KB: layernormed rows, all 8 batches
    __shared__ float Vsm[2][8][DK_];     // 8 KB: per-expert-slot V
    __shared__ float recsm[2][8][S_];    // 4 KB: V @ wout (pre-fused)
    __shared__ float scalesm[2][8];      // gate*aw + (1-aw)
    __shared__ float Vpsm[2][8][5];      // pentachoron projections (normalized)
    __shared__ float fusedsm[8];
    __shared__ float w_esm[2];
    __shared__ float awsm[2];
    __shared__ float invnsm[2][5];
    __shared__ int   eactsm[2];
    __shared__ int   nactsm;

    const int p    = blockIdx.x;
    const int tid  = threadIdx.x;
    const int warp = tid >> 5;
    const int lane = tid & 31;

    // ---------------- LayerNorm: warp w handles batch b = w ----------------
    {
        const int b = warp;
        const float4* xr = (const float4*)(x + ((size_t)b * P_ + p) * D_);
        float4 xv[8];
        float s = 0.f, ss = 0.f;
#pragma unroll
        for (int it = 0; it < 8; ++it) {
            xv[it] = __ldg(xr + it * 32 + lane);
            s  += xv[it].x + xv[it].y + xv[it].z + xv[it].w;
            ss += xv[it].x * xv[it].x + xv[it].y * xv[it].y
                + xv[it].z * xv[it].z + xv[it].w * xv[it].w;
        }
#pragma unroll
        for (int o = 16; o; o >>= 1) {
            s  += __shfl_xor_sync(~0u, s, o);
            ss += __shfl_xor_sync(~0u, ss, o);
        }
        const float mu   = s * (1.0f / D_);
        const float var  = ss * (1.0f / D_) - mu * mu;
        const float rstd = rsqrtf(var + 1e-5f);
        float4* xo = (float4*)xnsm[b];
#pragma unroll
        for (int it = 0; it < 8; ++it) {
            const int i4 = it * 32 + lane;
            const float4 g  = __ldg((const float4*)ln_gamma + i4);
            const float4 be = __ldg((const float4*)ln_beta + i4);
            float4 o4;
            o4.x = (xv[it].x - mu) * rstd * g.x + be.x;
            o4.y = (xv[it].y - mu) * rstd * g.y + be.y;
            o4.z = (xv[it].z - mu) * rstd * g.z + be.z;
            o4.w = (xv[it].w - mu) * rstd * g.w + be.w;
            xo[i4] = o4;
        }
    }

    // ------------- per-block scalar precompute (warp 0, after its LN) -------------
    if (warp == 0) {
        const float fp = __ldg(fingerprints + p);
        int n = 0;
        int ea[2] = {0, 0};
        const int base = (int)floorf(fp * 16.0f);
#pragma unroll
        for (int dd = -1; dd <= 1; ++dd) {
            const int e = base + dd;
            if (e < 0 || e >= E_) continue;
            const float fmn = fmaxf(0.0f, (float)e * (1.0f / 16.0f) - 0.03125f);
            const float fmx = fminf(1.0f, (float)(e + 1) * (1.0f / 16.0f) + 0.03125f);
            if (fp >= fmn && fp < fmx) { if (n < 2) ea[n] = e; ++n; }
        }
        if (n > 2) n = 2;
        for (int k = 0; k < n; ++k) {
            const int e = ea[k];
            // pos_w = sigmoid(mean(pos_embed[e]))
            const float4 pe = __ldg((const float4*)(pos_embed + e * DK_) + lane);
            float pm = pe.x + pe.y + pe.z + pe.w;
#pragma unroll
            for (int o = 16; o; o >>= 1) pm += __shfl_xor_sync(~0u, pm, o);
            const float pos_w = sigm(pm * (1.0f / DK_));
            // beta_w = 1 + sum(sigmoid(betas)*valid)/sum(valid)
            float sb = 0.f, cnt = 0.f;
#pragma unroll
            for (int kk = 0; kk < 4; ++kk) {
                const int off = (kk == 0) ? -2 : (kk == 1) ? -1 : (kk == 2) ? 1 : 2;
                const int nb = e + off;
                if (nb >= 0 && nb < E_) { sb += sigm(__ldg(betas + e * 4 + kk)); cnt += 1.f; }
            }
            const float we = pos_w * (1.0f + sb / cnt);
            // pentachoron inverse norms
#pragma unroll
            for (int v = 0; v < 5; ++v) {
                const float4 pv = __ldg((const float4*)(penta + e * 5 * DK_ + v * DK_) + lane);
                float nn = pv.x * pv.x + pv.y * pv.y + pv.z * pv.z + pv.w * pv.w;
#pragma unroll
                for (int o = 16; o; o >>= 1) nn += __shfl_xor_sync(~0u, nn, o);
                if (lane == 0) invnsm[k][v] = 1.0f / sqrtf(nn);
            }
            if (lane == 0) {
                w_esm[k]  = we;
                awsm[k]   = sigm(__ldg(alpha + e));
                eactsm[k] = e;
            }
        }
        if (lane == 0) nactsm = n;
    }
    __syncthreads();

    const int  nact = nactsm;
    const int  kgrp = tid >> 7;          // expert slot: 0 or 1
    const int  g    = tid & 127;         // index within group
    const bool act  = (kgrp < nact);
    const int  e    = act ? eactsm[kgrp] : 0;

    // ---------------- alpha gate: 128 threads/group = 16 h x 8 b ----------------
    if (act) {
        const int b = g >> 4, j = g & 15;
        const float* W1 = w1 + e * (S_ * H_);
        const float* xn = xnsm[b] + e * S_;
        float acc = __ldg(b1 + e * H_ + j);
#pragma unroll 8
        for (int s = 0; s < S_; ++s) acc += xn[s] * __ldg(W1 + s * H_ + j);
        const float h = gelu_exact(acc);
        float t = h * __ldg(w2 + e * H_ + j);
#pragma unroll
        for (int o = 8; o; o >>= 1) t += __shfl_down_sync(~0u, t, o, 16);
        if (j == 0) {
            const float gate = sigm(t + __ldg(b2 + e));
            const float aw   = awsm[kgrp];
            scalesm[kgrp][b] = gate * aw + (1.0f - aw);
        }
    }
    __syncthreads();

    // ---------------- V = scale * (feats @ wv), batch-blocked ----------------
    if (act) {
        const int d = g;
        const float* WV = wv + e * (S_ * DK_);
        float acc[8];
#pragma unroll
        for (int b = 0; b < 8; ++b) acc[b] = 0.f;
#pragma unroll
        for (int s4 = 0; s4 < S_ / 4; ++s4) {
            const float q0 = __ldg(WV + (s4 * 4 + 0) * DK_ + d);
            const float q1 = __ldg(WV + (s4 * 4 + 1) * DK_ + d);
            const float q2 = __ldg(WV + (s4 * 4 + 2) * DK_ + d);
            const float q3 = __ldg(WV + (s4 * 4 + 3) * DK_ + d);
#pragma unroll
            for (int b = 0; b < 8; ++b) {
                const float4 xf = *(const float4*)&xnsm[b][e * S_ + s4 * 4];
                acc[b] += xf.x * q0 + xf.y * q1 + xf.z * q2 + xf.w * q3;
            }
        }
#pragma unroll
        for (int b = 0; b < 8; ++b) Vsm[kgrp][b][d] = acc[b] * scalesm[kgrp][b];
    }
    __syncthreads();

    // ---------- rec = V @ wout (pre-fused), split d over 2 halves; + Vp ----------
    float racc[8];
    const int s_idx = g & 63, half = g >> 6;
    if (act) {
#pragma unroll
        for (int b = 0; b < 8; ++b) racc[b] = 0.f;
        const float* WO = wout + e * (DK_ * S_);
#pragma unroll
        for (int d4 = 0; d4 < 16; ++d4) {
            const int d = half * 64 + d4 * 4;
            const float q0 = __ldg(WO + (d + 0) * S_ + s_idx);
            const float q1 = __ldg(WO + (d + 1) * S_ + s_idx);
            const float q2 = __ldg(WO + (d + 2) * S_ + s_idx);
            const float q3 = __ldg(WO + (d + 3) * S_ + s_idx);
#pragma unroll
            for (int b = 0; b < 8; ++b) {
                const float4 vv = *(const float4*)&Vsm[kgrp][b][d];
                racc[b] += vv.x * q0 + vv.y * q1 + vv.z * q2 + vv.w * q3;
            }
        }
        if (half == 0) {
#pragma unroll
            for (int b = 0; b < 8; ++b) recsm[kgrp][b][s_idx] = racc[b];
        }
        // Vp: 40 threads per group, thread = (v, b)
        if (g < 40) {
            const int v = g / 8, b = g & 7;
            const float4* PE = (const float4*)(penta + e * 5 * DK_ + v * DK_);
            const float4* VV = (const float4*)Vsm[kgrp][b];
            float pacc = 0.f;
#pragma unroll
            for (int d4 = 0; d4 < 32; ++d4) {
                const float4 pv = __ldg(PE + d4);
                const float4 vv = VV[d4];
                pacc += pv.x * vv.x + pv.y * vv.y + pv.z * vv.z + pv.w * vv.w;
            }
            Vpsm[kgrp][b][v] = pacc * invnsm[kgrp][v];
        }
    }
    __syncthreads();

    if (act && half == 1) {
#pragma unroll
        for (int b = 0; b < 8; ++b) recsm[kgrp][b][s_idx] += racc[b];
    }
    // fused[b] = mean_v(num_v / den) / |T|
    if (tid < 8) {
        const int b = tid;
        float den = 0.f;
        for (int k = 0; k < nact; ++k) den += w_esm[k];
        den = fmaxf(den, 1e-6f);
        float fs = 0.f;
#pragma unroll
        for (int v = 0; v < 5; ++v) {
            float nv = 0.f;
            for (int k = 0; k < nact; ++k) nv += Vpsm[k][b][v] * w_esm[k];
            fs += nv / den;
        }
        fusedsm[b] = fs * 0.2f / fabsf(__ldg(temperature));
    }
    __syncthreads();

    // -------- epilogue: out = x + scatter(fused * rec into active slices) --------
    const int e0 = eactsm[0];
    const int e1 = (nact > 1) ? eactsm[1] : -1;
#pragma unroll
    for (int it = 0; it < 8; ++it) {
        const int idx4 = tid + it * 256;      // 0..2047 = 8 batches x 256 float4
        const int b  = idx4 >> 8;
        const int f4 = idx4 & 255;
        const int i  = f4 * 4;
        const int ee = i >> 6;
        const float4 xv = __ldg((const float4*)(x + ((size_t)b * P_ + p) * D_) + f4);
        float4 o4 = xv;
        const int kk = (ee == e0) ? 0 : ((ee == e1) ? 1 : -1);
        if (kk >= 0) {
            const float fu = fusedsm[b];
            const float4 rv = *(const float4*)&recsm[kk][b][i & 63];
            o4.x += fu * rv.x;
            o4.y += fu * rv.y;
            o4.z += fu * rv.z;
            o4.w += fu * rv.w;
        }
        ((float4*)(out + ((size_t)b * P_ + p) * D_))[f4] = o4;
    }
}

} // namespace

extern "C" void kernel_launch(void* const* d_in, const int* in_sizes, int n_in,
                              void* d_out, int out_size)
{
    (void)in_sizes; (void)n_in; (void)out_size;
    cantor_moe_kernel<<<P_, 256>>>(
        (const float*)d_in[0],   // x
        (const float*)d_in[1],   // fingerprints
        (const float*)d_in[2],   // ln_gamma
        (const float*)d_in[3],   // ln_beta
        (const float*)d_in[4],   // w1
        (const float*)d_in[5],   // b1
        (const float*)d_in[6],   // w2
        (const float*)d_in[7],   // b2
        (const float*)d_in[8],   // alpha
        (const float*)d_in[9],   // wv
        (const float*)d_in[10],  // penta
        (const float*)d_in[11],  // betas
        (const float*)d_in[12],  // wout
        (const float*)d_in[13],  // pos_embed
        (const float*)d_in[14],  // temperature
        (float*)d_out);
}

// round 5
// speedup vs baseline: 1.3660x; 1.3660x over previous
#include <cuda_runtime.h>
#include <math.h>

// CantorMoELayer — B=8, P=2048, D=1024, E=16, S=64, DK=128, H=16
// R5: slice-only LN smem (4KB vs 32KB), gate||V overlap with deferred scale,
// warp-parallel Vp dots with fused penta-norm, inline fused epilogue,
// 3 syncthreads, launch_bounds(256,4) to lift occupancy 3->4 CTAs/SM.

namespace {

constexpr int P_  = 2048;
constexpr int D_  = 1024;
constexpr int E_  = 16;
constexpr int S_  = 64;
constexpr int DK_ = 128;
constexpr int H_  = 16;

__device__ __forceinline__ float sigm(float x) { return 1.0f / (1.0f + expf(-x)); }
__device__ __forceinline__ float gelu_exact(float x) {
    return 0.5f * x * (1.0f + erff(x * 0.70710678118654752440f));
}

__global__ void __launch_bounds__(256, 4) cantor_moe_kernel(
    const float* __restrict__ x,
    const float* __restrict__ fingerprints,
    const float* __restrict__ ln_gamma,
    const float* __restrict__ ln_beta,
    const float* __restrict__ w1,
    const float* __restrict__ b1,
    const float* __restrict__ w2,
    const float* __restrict__ b2,
    const float* __restrict__ alpha,
    const float* __restrict__ wv,
    const float* __restrict__ penta,
    const float* __restrict__ betas,
    const float* __restrict__ wout,
    const float* __restrict__ pos_embed,
    const float* __restrict__ temperature,
    float* __restrict__ out)
{
    __shared__ float xnsm[2][8][S_];     // 4 KB: normalized ACTIVE slices only
    __shared__ float Vsm[2][8][DK_];     // 8 KB: unscaled V
    __shared__ float recA[2][8][S_];     // 4 KB: rec from d-half 0 (scaled)
    __shared__ float recB[2][8][S_];     // 4 KB: rec from d-half 1 (scaled)
    __shared__ float scalesm[2][8];      // gate*aw + (1-aw)
    __shared__ float Vpsm[2][8][5];      // scaled+normalized penta projections
    __shared__ float w_esm[2];

    const int p    = blockIdx.x;
    const int tid  = threadIdx.x;
    const int warp = tid >> 5;
    const int lane = tid & 31;

    // ---------------- expert selection: per-thread, redundant, no sync ----------------
    const float fp = __ldg(fingerprints + p);
    int nact = 0, e0 = 0, e1 = 0;
    {
        const int base = (int)floorf(fp * 16.0f);
#pragma unroll
        for (int dd = -1; dd <= 1; ++dd) {
            const int ee = base + dd;
            if (ee < 0 || ee >= E_) continue;
            const float fmn = fmaxf(0.0f, (float)ee * 0.0625f - 0.03125f);
            const float fmx = fminf(1.0f, (float)(ee + 1) * 0.0625f + 0.03125f);
            if (fp >= fmn && fp < fmx) {
                if (nact == 0) e0 = ee; else if (nact == 1) e1 = ee;
                ++nact;
            }
        }
        if (nact > 2) nact = 2;
    }

    // ---------------- LayerNorm: warp w = batch b; 2-pass (no retained row) ----------------
    {
        const int b = warp;
        const float* xr = x + ((size_t)b * P_ + p) * D_;
        float s = 0.f, ss = 0.f;
#pragma unroll
        for (int it = 0; it < 8; ++it) {
            const float4 xv = __ldg((const float4*)xr + it * 32 + lane);
            s  += xv.x + xv.y + xv.z + xv.w;
            ss += xv.x * xv.x + xv.y * xv.y + xv.z * xv.z + xv.w * xv.w;
        }
#pragma unroll
        for (int o = 16; o; o >>= 1) {
            s  += __shfl_xor_sync(~0u, s, o);
            ss += __shfl_xor_sync(~0u, ss, o);
        }
        const float mu   = s * (1.0f / D_);
        const float var  = ss * (1.0f / D_) - mu * mu;
        const float rstd = rsqrtf(var + 1e-5f);
        // pass B: write only the active slices. lanes 0-15 -> slot 0, 16-31 -> slot 1
        const int kk = lane >> 4;
        if (kk < nact) {
            const int ee = kk ? e1 : e0;
            const int f4 = ee * 16 + (lane & 15);
            const float4 xv = __ldg((const float4*)xr + f4);
            const float4 gm = __ldg((const float4*)ln_gamma + f4);
            const float4 bt = __ldg((const float4*)ln_beta + f4);
            float4 o4;
            o4.x = (xv.x - mu) * rstd * gm.x + bt.x;
            o4.y = (xv.y - mu) * rstd * gm.y + bt.y;
            o4.z = (xv.z - mu) * rstd * gm.z + bt.z;
            o4.w = (xv.w - mu) * rstd * gm.w + bt.w;
            *(float4*)&xnsm[kk][b][(lane & 15) * 4] = o4;
        }
    }
    __syncthreads();   // sync1: xn slices ready

    const int  k   = tid >> 7;           // expert slot 0/1
    const int  g   = tid & 127;
    const bool act = (k < nact);
    const int  e   = act ? (k ? e1 : e0) : 0;

    // ---------------- gate AND unscaled V (both depend only on xn) ----------------
    if (act) {
        // ---- alpha gate: (b, j) = (g>>4, g&15) ----
        {
            const int b = g >> 4, j = g & 15;
            const float* W1 = w1 + e * (S_ * H_);
            const float* xn = xnsm[k][b];
            float acc = __ldg(b1 + e * H_ + j);
#pragma unroll 8
            for (int s = 0; s < S_; ++s) acc += xn[s] * __ldg(W1 + s * H_ + j);
            float t = gelu_exact(acc) * __ldg(w2 + e * H_ + j);
#pragma unroll
            for (int o = 8; o; o >>= 1) t += __shfl_down_sync(~0u, t, o, 16);
            if (j == 0) {
                const float gate = sigm(t + __ldg(b2 + e));
                const float aw   = sigm(__ldg(alpha + e));
                scalesm[k][b] = gate * aw + (1.0f - aw);
            }
        }
        // ---- V unscaled: thread = d, batch-register-blocked ----
        {
            const int d = g;
            const float* WV = wv + e * (S_ * DK_);
            float acc[8];
#pragma unroll
            for (int b = 0; b < 8; ++b) acc[b] = 0.f;
#pragma unroll
            for (int s4 = 0; s4 < S_ / 4; ++s4) {
                const float q0 = __ldg(WV + (s4 * 4 + 0) * DK_ + d);
                const float q1 = __ldg(WV + (s4 * 4 + 1) * DK_ + d);
                const float q2 = __ldg(WV + (s4 * 4 + 2) * DK_ + d);
                const float q3 = __ldg(WV + (s4 * 4 + 3) * DK_ + d);
#pragma unroll
                for (int b = 0; b < 8; ++b) {
                    const float4 xf = *(const float4*)&xnsm[k][b][s4 * 4];
                    acc[b] += xf.x * q0 + xf.y * q1 + xf.z * q2 + xf.w * q3;
                }
            }
#pragma unroll
            for (int b = 0; b < 8; ++b) Vsm[k][b][d] = acc[b];
        }
    }
    __syncthreads();   // sync2: Vsm + scalesm ready

    // -------- rec (scale at write, 2 half-buffers) + warp-parallel Vp + w_e --------
    if (act) {
        const int s_idx = g & 63, half = g >> 6;
        {
            float racc[8];
#pragma unroll
            for (int b = 0; b < 8; ++b) racc[b] = 0.f;
            const float* WO = wout + e * (DK_ * S_) + half * 64 * S_;
#pragma unroll
            for (int d4 = 0; d4 < 16; ++d4) {
                const int d = d4 * 4;
                const float q0 = __ldg(WO + (d + 0) * S_ + s_idx);
                const float q1 = __ldg(WO + (d + 1) * S_ + s_idx);
                const float q2 = __ldg(WO + (d + 2) * S_ + s_idx);
                const float q3 = __ldg(WO + (d + 3) * S_ + s_idx);
#pragma unroll
                for (int b = 0; b < 8; ++b) {
                    const float4 vv = *(const float4*)&Vsm[k][b][half * 64 + d];
                    racc[b] += vv.x * q0 + vv.y * q1 + vv.z * q2 + vv.w * q3;
                }
            }
            if (half == 0) {
#pragma unroll
                for (int b = 0; b < 8; ++b) recA[k][b][s_idx] = racc[b] * scalesm[k][b];
            } else {
#pragma unroll
                for (int b = 0; b < 8; ++b) recB[k][b][s_idx] = racc[b] * scalesm[k][b];
            }
        }
        // ---- Vp: each warp of the group takes 10 of 40 (v,b) pairs; lane = d-quad ----
        {
            const int wg = g >> 5;
#pragma unroll
            for (int t = 0; t < 10; ++t) {
                const int idx = wg * 10 + t;          // 0..39
                const int v = idx >> 3, b = idx & 7;
                const float4 pv = __ldg((const float4*)(penta + (e * 5 + v) * DK_) + lane);
                const float4 vv = *(const float4*)&Vsm[k][b][lane * 4];
                float pd = pv.x * vv.x + pv.y * vv.y + pv.z * vv.z + pv.w * vv.w;
                float nn = pv.x * pv.x + pv.y * pv.y + pv.z * pv.z + pv.w * pv.w;
#pragma unroll
                for (int o = 16; o; o >>= 1) {
                    pd += __shfl_xor_sync(~0u, pd, o);
                    nn += __shfl_xor_sync(~0u, nn, o);
                }
                if (lane == 0)
                    Vpsm[k][b][v] = pd * rsqrtf(nn) * scalesm[k][b];
            }
            // ---- w_e (warp 0 of each group) ----
            if (wg == 0) {
                const float4 pe = __ldg((const float4*)(pos_embed + e * DK_) + lane);
                float pm = pe.x + pe.y + pe.z + pe.w;
#pragma unroll
                for (int o = 16; o; o >>= 1) pm += __shfl_xor_sync(~0u, pm, o);
                if (lane == 0) {
                    float sb = 0.f, cnt = 0.f;
#pragma unroll
                    for (int kk = 0; kk < 4; ++kk) {
                        const int off = (kk == 0) ? -2 : (kk == 1) ? -1 : (kk == 2) ? 1 : 2;
                        const int nb = e + off;
                        if (nb >= 0 && nb < E_) { sb += sigm(__ldg(betas + e * 4 + kk)); cnt += 1.f; }
                    }
                    w_esm[k] = sigm(pm * (1.0f / DK_)) * (1.0f + sb / cnt);
                }
            }
        }
    }
    __syncthreads();   // sync3: recA/recB, Vpsm, w_esm ready

    // -------- epilogue: inline fused; out = x + fused * rec on active slices --------
    {
        const int b = tid >> 5;              // one warp per batch
        float den = 0.f;
        for (int kk = 0; kk < nact; ++kk) den += w_esm[kk];
        den = fmaxf(den, 1e-6f);
        float fs = 0.f;
#pragma unroll
        for (int v = 0; v < 5; ++v) {
            float nv = 0.f;
            for (int kk = 0; kk < nact; ++kk) nv += Vpsm[kk][b][v] * w_esm[kk];
            fs += nv;
        }
        const float fused = (fs / den) * 0.2f / fabsf(__ldg(temperature));

        const float* xr = x   + ((size_t)b * P_ + p) * D_;
        float*       orw = out + ((size_t)b * P_ + p) * D_;
#pragma unroll
        for (int it = 0; it < 8; ++it) {
            const int f4 = it * 32 + lane;          // float4 index in the row
            float4 xv = __ldg((const float4*)xr + f4);
            const int ee = f4 >> 4;                 // 16 float4 per expert slice
            const int kk = (ee == e0) ? 0 : ((nact > 1 && ee == e1) ? 1 : -1);
            if (kk >= 0) {
                const int si = (f4 & 15) * 4;
                const float4 ra = *(const float4*)&recA[kk][b][si];
                const float4 rb = *(const float4*)&recB[kk][b][si];
                xv.x += fused * (ra.x + rb.x);
                xv.y += fused * (ra.y + rb.y);
                xv.z += fused * (ra.z + rb.z);
                xv.w += fused * (ra.w + rb.w);
            }
            ((float4*)orw)[f4] = xv;
        }
    }
}

} // namespace

extern "C" void kernel_launch(void* const* d_in, const int* in_sizes, int n_in,
                              void* d_out, int out_size)
{
    (void)in_sizes; (void)n_in; (void)out_size;
    cantor_moe_kernel<<<P_, 256>>>(
        (const float*)d_in[0],   // x
        (const float*)d_in[1],   // fingerprints
        (const float*)d_in[2],   // ln_gamma
        (const float*)d_in[3],   // ln_beta
        (const float*)d_in[4],   // w1
        (const float*)d_in[5],   // b1
        (const float*)d_in[6],   // w2
        (const float*)d_in[7],   // b2
        (const float*)d_in[8],   // alpha
        (const float*)d_in[9],   // wv
        (const float*)d_in[10],  // penta
        (const float*)d_in[11],  // betas
        (const float*)d_in[12],  // wout
        (const float*)d_in[13],  // pos_embed
        (const float*)d_in[14],  // temperature
        (float*)d_out);
}